// round 1
// baseline (speedup 1.0000x reference)
#include <cuda_runtime.h>
#include <math.h>

// Problem constants
constexpr int kT   = 1024;   // tokens
constexpr int kH   = 1024;   // hidden
constexpr int kI   = 512;    // routed intermediate
constexpr int kE   = 16;     // routed experts
constexpr int kTopK = 4;
constexpr int kNG  = 4;      // n_group
constexpr int kGS  = kE / kNG; // experts per group = 4
constexpr int kTKG = 2;      // topk_group
constexpr int kISH = 1024;   // shared intermediate
constexpr float kScale = 2.5f;

// ---- device scratch (allowed: __device__ globals, no runtime allocation) ----
__device__ int   g_cnt[kE];
__device__ int   g_tok[kE * kT];
__device__ float g_coef[kE * kT];
__device__ float g_h[(size_t)kE * kT * kI];   // per-assignment silu(g)*u * coef  (33.5 MB)
__device__ float g_hs[(size_t)kT * kISH];     // shared-expert hidden (4 MB)

// ---------------------------------------------------------------------------
__global__ void zero_cnt_kernel() {
    if (threadIdx.x < kE) g_cnt[threadIdx.x] = 0;
}

// ---------------------------------------------------------------------------
// Router: one block per token. 16 warps -> 16 logits. Thread 0 does the
// grouped top-k (E=16, scalar) and scatters assignments.
__global__ __launch_bounds__(512) void router_kernel(
    const float* __restrict__ x, const float* __restrict__ rw,
    const float* __restrict__ ebias)
{
    const int t = blockIdx.x;
    const int warp = threadIdx.x >> 5;
    const int lane = threadIdx.x & 31;
    __shared__ float logits[kE];

    const float* xr = x + (size_t)t * kH;
    float acc = 0.f;
    for (int h = lane; h < kH; h += 32)
        acc += xr[h] * rw[h * kE + warp];
    #pragma unroll
    for (int o = 16; o; o >>= 1) acc += __shfl_xor_sync(0xffffffffu, acc, o);
    if (lane == 0) logits[warp] = acc;
    __syncthreads();

    if (threadIdx.x == 0) {
        float scores[kE], sc[kE];
        #pragma unroll
        for (int e = 0; e < kE; e++) {
            float s = 1.f / (1.f + expf(-logits[e]));
            scores[e] = s;
            sc[e] = s + ebias[e];
        }
        // group score = sum of top-2 within each group of 4
        float gs[kNG];
        #pragma unroll
        for (int g = 0; g < kNG; g++) {
            float m1 = -1e30f, m2 = -1e30f;
            #pragma unroll
            for (int j = 0; j < kGS; j++) {
                float v = sc[g * kGS + j];
                if (v > m1) { m2 = m1; m1 = v; }
                else if (v > m2) m2 = v;
            }
            gs[g] = m1 + m2;
        }
        // top-2 groups (strict >, lowest index on tie -> matches lax.top_k)
        bool gsel[kNG] = {false, false, false, false};
        for (int k = 0; k < kTKG; k++) {
            int bi = -1; float bv = -1e30f;
            for (int g = 0; g < kNG; g++)
                if (!gsel[g] && gs[g] > bv) { bv = gs[g]; bi = g; }
            gsel[bi] = true;
        }
        float masked[kE];
        #pragma unroll
        for (int e = 0; e < kE; e++)
            masked[e] = gsel[e / kGS] ? sc[e] : 0.f;
        // top-4 of masked (over all E, like the reference)
        int   tidx[kTopK];
        float w[kTopK];
        float wsum = 0.f;
        bool used[kE];
        #pragma unroll
        for (int e = 0; e < kE; e++) used[e] = false;
        for (int k = 0; k < kTopK; k++) {
            int bi = -1; float bv = -1e30f;
            for (int e = 0; e < kE; e++)
                if (!used[e] && masked[e] > bv) { bv = masked[e]; bi = e; }
            used[bi] = true;
            tidx[k] = bi;
            w[k] = scores[bi];    // weights use UNbiased scores
            wsum += w[k];
        }
        float inv = kScale / (wsum + 1e-20f);
        for (int k = 0; k < kTopK; k++) {
            int e = tidx[k];
            int slot = atomicAdd(&g_cnt[e], 1);
            g_tok[e * kT + slot]  = t;
            g_coef[e * kT + slot] = w[k] * inv;
        }
    }
}

// ---------------------------------------------------------------------------
// Routed gate+up: gathered 64x64 tile GEMM, fused SiLU, coef folded into h.
__global__ __launch_bounds__(256) void gateup_routed(
    const float* __restrict__ x, const float* __restrict__ wg,
    const float* __restrict__ wu)
{
    const int e = blockIdx.z;
    const int cnt = g_cnt[e];
    const int row0 = blockIdx.y * 64;
    if (row0 >= cnt) return;
    const int col0 = blockIdx.x * 64;

    __shared__ float As[16][65];
    __shared__ float Bg[16][64];
    __shared__ float Bu[16][64];

    const int tid = threadIdx.x;
    const int tx = tid & 15, ty = tid >> 4;
    const int akk = tid & 15, am = tid >> 4;
    const int bk = tid >> 4, bc = (tid & 15) * 4;

    const float* xrow[4];
    #pragma unroll
    for (int p = 0; p < 4; p++) {
        int r = row0 + am + p * 16;
        xrow[p] = (r < cnt) ? (x + (size_t)g_tok[e * kT + r] * kH) : nullptr;
    }
    const float* wg_e = wg + (size_t)e * kH * kI + col0 + bc;
    const float* wu_e = wu + (size_t)e * kH * kI + col0 + bc;

    float accg[4][4] = {}, accu[4][4] = {};

    for (int k0 = 0; k0 < kH; k0 += 16) {
        #pragma unroll
        for (int p = 0; p < 4; p++) {
            int m = am + p * 16;
            As[akk][m] = xrow[p] ? xrow[p][k0 + akk] : 0.f;
        }
        *(float4*)&Bg[bk][bc] = *(const float4*)&wg_e[(size_t)(k0 + bk) * kI];
        *(float4*)&Bu[bk][bc] = *(const float4*)&wu_e[(size_t)(k0 + bk) * kI];
        __syncthreads();
        #pragma unroll
        for (int kk = 0; kk < 16; kk++) {
            float a[4];
            #pragma unroll
            for (int r = 0; r < 4; r++) a[r] = As[kk][ty * 4 + r];
            float4 bgv = *(float4*)&Bg[kk][tx * 4];
            float4 buv = *(float4*)&Bu[kk][tx * 4];
            #pragma unroll
            for (int r = 0; r < 4; r++) {
                accg[r][0] += a[r] * bgv.x; accg[r][1] += a[r] * bgv.y;
                accg[r][2] += a[r] * bgv.z; accg[r][3] += a[r] * bgv.w;
                accu[r][0] += a[r] * buv.x; accu[r][1] += a[r] * buv.y;
                accu[r][2] += a[r] * buv.z; accu[r][3] += a[r] * buv.w;
            }
        }
        __syncthreads();
    }

    #pragma unroll
    for (int r = 0; r < 4; r++) {
        int rowi = row0 + ty * 4 + r;
        if (rowi < cnt) {
            float coef = g_coef[e * kT + rowi];
            float* hp = g_h + ((size_t)e * kT + rowi) * kI + col0 + tx * 4;
            #pragma unroll
            for (int c = 0; c < 4; c++) {
                float g = accg[r][c];
                float s = g / (1.f + expf(-g));
                hp[c] = coef * s * accu[r][c];
            }
        }
    }
}

// ---------------------------------------------------------------------------
// Routed down-proj: [cnt x I] @ [I x H], atomicAdd scatter into out.
__global__ __launch_bounds__(256) void down_routed(
    const float* __restrict__ wd, float* __restrict__ out)
{
    const int e = blockIdx.z;
    const int cnt = g_cnt[e];
    const int row0 = blockIdx.y * 64;
    if (row0 >= cnt) return;
    const int col0 = blockIdx.x * 64;

    __shared__ float As[16][65];
    __shared__ float Bs[16][64];

    const int tid = threadIdx.x;
    const int tx = tid & 15, ty = tid >> 4;
    const int akk = tid & 15, am = tid >> 4;
    const int bk = tid >> 4, bc = (tid & 15) * 4;

    const float* hbase = g_h + (size_t)e * kT * kI;
    const float* wd_e = wd + (size_t)e * kI * kH + col0 + bc;

    float acc[4][4] = {};
    for (int k0 = 0; k0 < kI; k0 += 16) {
        #pragma unroll
        for (int p = 0; p < 4; p++) {
            int m = am + p * 16;
            int r = row0 + m;
            As[akk][m] = (r < cnt) ? hbase[(size_t)r * kI + k0 + akk] : 0.f;
        }
        *(float4*)&Bs[bk][bc] = *(const float4*)&wd_e[(size_t)(k0 + bk) * kH];
        __syncthreads();
        #pragma unroll
        for (int kk = 0; kk < 16; kk++) {
            float a[4];
            #pragma unroll
            for (int r = 0; r < 4; r++) a[r] = As[kk][ty * 4 + r];
            float4 bv = *(float4*)&Bs[kk][tx * 4];
            #pragma unroll
            for (int r = 0; r < 4; r++) {
                acc[r][0] += a[r] * bv.x; acc[r][1] += a[r] * bv.y;
                acc[r][2] += a[r] * bv.z; acc[r][3] += a[r] * bv.w;
            }
        }
        __syncthreads();
    }
    #pragma unroll
    for (int r = 0; r < 4; r++) {
        int rowi = row0 + ty * 4 + r;
        if (rowi < cnt) {
            int tok = g_tok[e * kT + rowi];
            float* op = out + (size_t)tok * kH + col0 + tx * 4;
            #pragma unroll
            for (int c = 0; c < 4; c++) atomicAdd(&op[c], acc[r][c]);
        }
    }
}

// ---------------------------------------------------------------------------
// Shared expert gate+up: plain [T x H] @ [H x ISH] fused SiLU.
__global__ __launch_bounds__(256) void gateup_shared(
    const float* __restrict__ x, const float* __restrict__ swg,
    const float* __restrict__ swu)
{
    const int row0 = blockIdx.y * 64;
    const int col0 = blockIdx.x * 64;

    __shared__ float As[16][65];
    __shared__ float Bg[16][64];
    __shared__ float Bu[16][64];

    const int tid = threadIdx.x;
    const int tx = tid & 15, ty = tid >> 4;
    const int akk = tid & 15, am = tid >> 4;
    const int bk = tid >> 4, bc = (tid & 15) * 4;

    const float* swg_p = swg + col0 + bc;
    const float* swu_p = swu + col0 + bc;

    float accg[4][4] = {}, accu[4][4] = {};
    for (int k0 = 0; k0 < kH; k0 += 16) {
        #pragma unroll
        for (int p = 0; p < 4; p++) {
            int m = am + p * 16;
            As[akk][m] = x[(size_t)(row0 + m) * kH + k0 + akk];
        }
        *(float4*)&Bg[bk][bc] = *(const float4*)&swg_p[(size_t)(k0 + bk) * kISH];
        *(float4*)&Bu[bk][bc] = *(const float4*)&swu_p[(size_t)(k0 + bk) * kISH];
        __syncthreads();
        #pragma unroll
        for (int kk = 0; kk < 16; kk++) {
            float a[4];
            #pragma unroll
            for (int r = 0; r < 4; r++) a[r] = As[kk][ty * 4 + r];
            float4 bgv = *(float4*)&Bg[kk][tx * 4];
            float4 buv = *(float4*)&Bu[kk][tx * 4];
            #pragma unroll
            for (int r = 0; r < 4; r++) {
                accg[r][0] += a[r] * bgv.x; accg[r][1] += a[r] * bgv.y;
                accg[r][2] += a[r] * bgv.z; accg[r][3] += a[r] * bgv.w;
                accu[r][0] += a[r] * buv.x; accu[r][1] += a[r] * buv.y;
                accu[r][2] += a[r] * buv.z; accu[r][3] += a[r] * buv.w;
            }
        }
        __syncthreads();
    }
    #pragma unroll
    for (int r = 0; r < 4; r++) {
        int rowi = row0 + ty * 4 + r;
        float* hp = g_hs + (size_t)rowi * kISH + col0 + tx * 4;
        #pragma unroll
        for (int c = 0; c < 4; c++) {
            float g = accg[r][c];
            float s = g / (1.f + expf(-g));
            hp[c] = s * accu[r][c];
        }
    }
}

// ---------------------------------------------------------------------------
// Shared expert down-proj: [T x ISH] @ [ISH x H] -> writes out (initializes it).
__global__ __launch_bounds__(256) void down_shared(
    const float* __restrict__ swd, float* __restrict__ out)
{
    const int row0 = blockIdx.y * 64;
    const int col0 = blockIdx.x * 64;

    __shared__ float As[16][65];
    __shared__ float Bs[16][64];

    const int tid = threadIdx.x;
    const int tx = tid & 15, ty = tid >> 4;
    const int akk = tid & 15, am = tid >> 4;
    const int bk = tid >> 4, bc = (tid & 15) * 4;

    const float* swd_p = swd + col0 + bc;

    float acc[4][4] = {};
    for (int k0 = 0; k0 < kISH; k0 += 16) {
        #pragma unroll
        for (int p = 0; p < 4; p++) {
            int m = am + p * 16;
            As[akk][m] = g_hs[(size_t)(row0 + m) * kISH + k0 + akk];
        }
        *(float4*)&Bs[bk][bc] = *(const float4*)&swd_p[(size_t)(k0 + bk) * kH];
        __syncthreads();
        #pragma unroll
        for (int kk = 0; kk < 16; kk++) {
            float a[4];
            #pragma unroll
            for (int r = 0; r < 4; r++) a[r] = As[kk][ty * 4 + r];
            float4 bv = *(float4*)&Bs[kk][tx * 4];
            #pragma unroll
            for (int r = 0; r < 4; r++) {
                acc[r][0] += a[r] * bv.x; acc[r][1] += a[r] * bv.y;
                acc[r][2] += a[r] * bv.z; acc[r][3] += a[r] * bv.w;
            }
        }
        __syncthreads();
    }
    #pragma unroll
    for (int r = 0; r < 4; r++) {
        int rowi = row0 + ty * 4 + r;
        float* op = out + (size_t)rowi * kH + col0 + tx * 4;
        #pragma unroll
        for (int c = 0; c < 4; c++) op[c] = acc[r][c];
    }
}

// ---------------------------------------------------------------------------
extern "C" void kernel_launch(void* const* d_in, const int* in_sizes, int n_in,
                              void* d_out, int out_size) {
    const float* x   = (const float*)d_in[0];
    const float* rw  = (const float*)d_in[1];
    const float* eb  = (const float*)d_in[2];
    const float* wg  = (const float*)d_in[3];
    const float* wu  = (const float*)d_in[4];
    const float* wd  = (const float*)d_in[5];
    const float* swg = (const float*)d_in[6];
    const float* swu = (const float*)d_in[7];
    const float* swd = (const float*)d_in[8];
    float* out = (float*)d_out;

    zero_cnt_kernel<<<1, 32>>>();
    router_kernel<<<kT, 512>>>(x, rw, eb);
    // shared expert writes out first (plain stores initialize every element)
    gateup_shared<<<dim3(kISH / 64, kT / 64), 256>>>(x, swg, swu);
    down_shared<<<dim3(kH / 64, kT / 64), 256>>>(swd, out);
    // routed experts accumulate on top via atomics
    gateup_routed<<<dim3(kI / 64, kT / 64, kE), 256>>>(x, wg, wu);
    down_routed<<<dim3(kH / 64, kT / 64, kE), 256>>>(wd, out);
}

// round 2
// speedup vs baseline: 4.0529x; 4.0529x over previous
#include <cuda_runtime.h>
#include <math.h>
#include <stdint.h>

// Problem constants
constexpr int kT    = 1024;   // tokens
constexpr int kH    = 1024;   // hidden
constexpr int kI    = 512;    // routed intermediate
constexpr int kE    = 16;     // routed experts
constexpr int kEAll = 18;     // + 2 shared-expert halves
constexpr int kTopK = 4;
constexpr int kNG   = 4;
constexpr int kGS   = kE / kNG;
constexpr int kTKG  = 2;
constexpr int kISH  = 1024;   // shared intermediate (= 2 * kI)
constexpr float kScale = 2.5f;

// ---- device scratch ----
__device__ int   g_cnt[kEAll];
__device__ int   g_tok[kEAll * kT];
__device__ float g_coef[kEAll * kT];
__device__ float g_h[(size_t)kEAll * kT * kI];   // 37.7 MB

// ---------------------------------------------------------------------------
__device__ __forceinline__ float tf32r(float f) {
    uint32_t r; asm("cvt.rna.tf32.f32 %0, %1;" : "=r"(r) : "f"(f));
    return __uint_as_float(r);
}

__device__ __forceinline__ void mma8(float& c0, float& c1, float& c2, float& c3,
                                     uint32_t a0, uint32_t a1, uint32_t a2, uint32_t a3,
                                     uint32_t b0, uint32_t b1) {
    asm volatile("mma.sync.aligned.m16n8k8.row.col.f32.tf32.tf32.f32 "
                 "{%0,%1,%2,%3},{%4,%5,%6,%7},{%8,%9},{%0,%1,%2,%3};\n"
                 : "+f"(c0), "+f"(c1), "+f"(c2), "+f"(c3)
                 : "r"(a0), "r"(a1), "r"(a2), "r"(a3), "r"(b0), "r"(b1));
}

// ---------------------------------------------------------------------------
__global__ void init_kernel() {
    int i = blockIdx.x * blockDim.x + threadIdx.x;
    if (i < kE) g_cnt[i] = 0;
    if (i == kE || i == kE + 1) g_cnt[i] = kT;
    if (i < kT) {
        g_tok[kE * kT + i] = i;       g_coef[kE * kT + i] = 1.f;
        g_tok[(kE + 1) * kT + i] = i; g_coef[(kE + 1) * kT + i] = 1.f;
    }
}

__global__ void zero_out_kernel(float4* out) {
    int i = blockIdx.x * blockDim.x + threadIdx.x;
    if (i < kT * kH / 4) out[i] = make_float4(0.f, 0.f, 0.f, 0.f);
}

// ---------------------------------------------------------------------------
// Router: one block per token; exact grouped-top-k, scatter with atomics.
__global__ __launch_bounds__(512) void router_kernel(
    const float* __restrict__ x, const float* __restrict__ rw,
    const float* __restrict__ ebias)
{
    const int t = blockIdx.x;
    const int warp = threadIdx.x >> 5;
    const int lane = threadIdx.x & 31;
    __shared__ float logits[kE];

    const float* xr = x + (size_t)t * kH;
    float acc = 0.f;
    for (int h = lane; h < kH; h += 32)
        acc += xr[h] * rw[h * kE + warp];
    #pragma unroll
    for (int o = 16; o; o >>= 1) acc += __shfl_xor_sync(0xffffffffu, acc, o);
    if (lane == 0) logits[warp] = acc;
    __syncthreads();

    if (threadIdx.x == 0) {
        float scores[kE], sc[kE];
        #pragma unroll
        for (int e = 0; e < kE; e++) {
            float s = 1.f / (1.f + expf(-logits[e]));
            scores[e] = s;
            sc[e] = s + ebias[e];
        }
        float gs[kNG];
        #pragma unroll
        for (int g = 0; g < kNG; g++) {
            float m1 = -1e30f, m2 = -1e30f;
            #pragma unroll
            for (int j = 0; j < kGS; j++) {
                float v = sc[g * kGS + j];
                if (v > m1) { m2 = m1; m1 = v; }
                else if (v > m2) m2 = v;
            }
            gs[g] = m1 + m2;
        }
        bool gsel[kNG] = {false, false, false, false};
        for (int k = 0; k < kTKG; k++) {
            int bi = -1; float bv = -1e30f;
            for (int g = 0; g < kNG; g++)
                if (!gsel[g] && gs[g] > bv) { bv = gs[g]; bi = g; }
            gsel[bi] = true;
        }
        float masked[kE];
        #pragma unroll
        for (int e = 0; e < kE; e++)
            masked[e] = gsel[e / kGS] ? sc[e] : 0.f;
        int tidx[kTopK]; float w[kTopK]; float wsum = 0.f;
        bool used[kE];
        #pragma unroll
        for (int e = 0; e < kE; e++) used[e] = false;
        for (int k = 0; k < kTopK; k++) {
            int bi = -1; float bv = -1e30f;
            for (int e = 0; e < kE; e++)
                if (!used[e] && masked[e] > bv) { bv = masked[e]; bi = e; }
            used[bi] = true;
            tidx[k] = bi;
            w[k] = scores[bi];
            wsum += w[k];
        }
        float inv = kScale / (wsum + 1e-20f);
        for (int k = 0; k < kTopK; k++) {
            int e = tidx[k];
            int slot = atomicAdd(&g_cnt[e], 1);
            g_tok[e * kT + slot]  = t;
            g_coef[e * kT + slot] = w[k] * inv;
        }
    }
}

// ---------------------------------------------------------------------------
// Fused gate+up for all 18 experts. Block tile: 128 rows x (64 g + 64 u cols).
// tf32 mma m16n8k8, 8 warps (4M x 2N), warp tile 32x32 on each of g/u.
__global__ __launch_bounds__(256) void gateup_all(
    const float* __restrict__ x, const float* __restrict__ wg,
    const float* __restrict__ wu, const float* __restrict__ swg,
    const float* __restrict__ swu)
{
    const int e = blockIdx.z;
    const int cnt = g_cnt[e];
    const int row0 = blockIdx.y * 128;
    if (row0 >= cnt) return;
    const int col0 = blockIdx.x * 64;

    const float *bg, *bu; int ldb;
    if (e < kE) {
        bg = wg + (size_t)e * kH * kI;
        bu = wu + (size_t)e * kH * kI;
        ldb = kI;
    } else {
        int off = (e - kE) * kI;
        bg = swg + off; bu = swu + off; ldb = kISH;
    }

    __shared__ float As[128 * 20];   // [m][k], stride 20 (conflict-free)
    __shared__ float Bgs[16 * 68];   // [k][n], stride 68
    __shared__ float Bus[16 * 68];

    const int tid = threadIdx.x;

    // A staging: 2 float4/thread (gathered token rows)
    const float* aptr[2]; bool aval[2]; int asoff[2];
    #pragma unroll
    for (int p = 0; p < 2; p++) {
        int j = tid + 256 * p;
        int arow = j >> 2, ac4 = j & 3;
        int r = row0 + arow;
        aval[p] = r < cnt;
        int tok = aval[p] ? g_tok[e * kT + r] : 0;
        aptr[p] = x + (size_t)tok * kH + ac4 * 4;
        asoff[p] = arow * 20 + ac4 * 4;
    }
    // B staging: 1 float4/thread per matrix
    const int bkrow = tid >> 4, bc4 = tid & 15;
    const float* bgp = bg + (size_t)bkrow * ldb + col0 + bc4 * 4;
    const float* bup = bu + (size_t)bkrow * ldb + col0 + bc4 * 4;
    const int bsoff = bkrow * 68 + bc4 * 4;

    const int warp = tid >> 5, lane = tid & 31;
    const int mb = (warp & 3) * 32, nb = (warp >> 2) * 32;
    const int qr = lane >> 2, qc = lane & 3;

    float cg[2][4][4] = {}, cu[2][4][4] = {};

    float4 ra[2], rbg, rbu;
    #pragma unroll
    for (int p = 0; p < 2; p++)
        ra[p] = aval[p] ? *(const float4*)aptr[p] : make_float4(0.f,0.f,0.f,0.f);
    rbg = *(const float4*)bgp;
    rbu = *(const float4*)bup;

    for (int k0 = 0; k0 < kH; k0 += 16) {
        #pragma unroll
        for (int p = 0; p < 2; p++) {
            float4 v;
            v.x = tf32r(ra[p].x); v.y = tf32r(ra[p].y);
            v.z = tf32r(ra[p].z); v.w = tf32r(ra[p].w);
            *(float4*)&As[asoff[p]] = v;
        }
        {
            float4 v;
            v.x = tf32r(rbg.x); v.y = tf32r(rbg.y);
            v.z = tf32r(rbg.z); v.w = tf32r(rbg.w);
            *(float4*)&Bgs[bsoff] = v;
        }
        {
            float4 v;
            v.x = tf32r(rbu.x); v.y = tf32r(rbu.y);
            v.z = tf32r(rbu.z); v.w = tf32r(rbu.w);
            *(float4*)&Bus[bsoff] = v;
        }
        __syncthreads();
        if (k0 + 16 < kH) {
            #pragma unroll
            for (int p = 0; p < 2; p++)
                ra[p] = aval[p] ? *(const float4*)(aptr[p] + k0 + 16)
                                : make_float4(0.f,0.f,0.f,0.f);
            rbg = *(const float4*)(bgp + (size_t)(k0 + 16) * ldb);
            rbu = *(const float4*)(bup + (size_t)(k0 + 16) * ldb);
        }
        #pragma unroll
        for (int ks = 0; ks < 16; ks += 8) {
            uint32_t af[2][4];
            #pragma unroll
            for (int mt = 0; mt < 2; mt++) {
                int m = mb + mt * 16;
                af[mt][0] = __float_as_uint(As[(m + qr) * 20 + ks + qc]);
                af[mt][1] = __float_as_uint(As[(m + qr + 8) * 20 + ks + qc]);
                af[mt][2] = __float_as_uint(As[(m + qr) * 20 + ks + qc + 4]);
                af[mt][3] = __float_as_uint(As[(m + qr + 8) * 20 + ks + qc + 4]);
            }
            #pragma unroll
            for (int nt = 0; nt < 4; nt++) {
                int n = nb + nt * 8 + qr;
                uint32_t b0g = __float_as_uint(Bgs[(ks + qc) * 68 + n]);
                uint32_t b1g = __float_as_uint(Bgs[(ks + qc + 4) * 68 + n]);
                uint32_t b0u = __float_as_uint(Bus[(ks + qc) * 68 + n]);
                uint32_t b1u = __float_as_uint(Bus[(ks + qc + 4) * 68 + n]);
                #pragma unroll
                for (int mt = 0; mt < 2; mt++) {
                    mma8(cg[mt][nt][0], cg[mt][nt][1], cg[mt][nt][2], cg[mt][nt][3],
                         af[mt][0], af[mt][1], af[mt][2], af[mt][3], b0g, b1g);
                    mma8(cu[mt][nt][0], cu[mt][nt][1], cu[mt][nt][2], cu[mt][nt][3],
                         af[mt][0], af[mt][1], af[mt][2], af[mt][3], b0u, b1u);
                }
            }
        }
        __syncthreads();
    }

    // Epilogue: h = coef * silu(g) * u, tf32-pre-rounded for the down GEMM.
    #pragma unroll
    for (int mt = 0; mt < 2; mt++) {
        #pragma unroll
        for (int half = 0; half < 2; half++) {
            int r = row0 + mb + mt * 16 + qr + half * 8;
            if (r < cnt) {
                float cf = g_coef[e * kT + r];
                float* hp = g_h + ((size_t)e * kT + r) * kI + col0;
                #pragma unroll
                for (int nt = 0; nt < 4; nt++) {
                    float g0 = cg[mt][nt][half * 2 + 0];
                    float g1 = cg[mt][nt][half * 2 + 1];
                    float u0 = cu[mt][nt][half * 2 + 0];
                    float u1 = cu[mt][nt][half * 2 + 1];
                    float h0 = cf * (g0 / (1.f + __expf(-g0))) * u0;
                    float h1 = cf * (g1 / (1.f + __expf(-g1))) * u1;
                    float2 st; st.x = tf32r(h0); st.y = tf32r(h1);
                    *(float2*)&hp[nb + nt * 8 + 2 * qc] = st;
                }
            }
        }
    }
}

// ---------------------------------------------------------------------------
// Down-proj for all 18 experts. Block tile 128x128, warp tile 32x64.
// Accumulates into zero-initialized out via atomicAdd (routed + shared).
__global__ __launch_bounds__(256) void down_all(
    const float* __restrict__ wd, const float* __restrict__ swd,
    float* __restrict__ out)
{
    const int e = blockIdx.z;
    const int cnt = g_cnt[e];
    const int row0 = blockIdx.y * 128;
    if (row0 >= cnt) return;
    const int col0 = blockIdx.x * 128;

    const float* bb = (e < kE) ? (wd + (size_t)e * kI * kH)
                               : (swd + (size_t)(e - kE) * kI * kH);

    __shared__ float As[128 * 20];   // [m][k]
    __shared__ float Bs[16 * 132];   // [k][n]

    const int tid = threadIdx.x;

    const float* aptr[2]; bool aval[2]; int asoff[2];
    #pragma unroll
    for (int p = 0; p < 2; p++) {
        int j = tid + 256 * p;
        int arow = j >> 2, ac4 = j & 3;
        int r = row0 + arow;
        aval[p] = r < cnt;
        int rc = aval[p] ? r : 0;
        aptr[p] = g_h + ((size_t)e * kT + rc) * kI + ac4 * 4;
        asoff[p] = arow * 20 + ac4 * 4;
    }
    const float* bptr[2]; int bsoff[2];
    #pragma unroll
    for (int p = 0; p < 2; p++) {
        int j = tid + 256 * p;
        int bkr = j >> 5, bc4 = j & 31;
        bptr[p] = bb + (size_t)bkr * kH + col0 + bc4 * 4;
        bsoff[p] = bkr * 132 + bc4 * 4;
    }

    const int warp = tid >> 5, lane = tid & 31;
    const int mb = (warp & 3) * 32, nbase = (warp >> 2) * 64;
    const int qr = lane >> 2, qc = lane & 3;

    float c[2][8][4] = {};

    float4 ra[2], rb[2];
    #pragma unroll
    for (int p = 0; p < 2; p++) {
        ra[p] = aval[p] ? *(const float4*)aptr[p] : make_float4(0.f,0.f,0.f,0.f);
        rb[p] = *(const float4*)bptr[p];
    }

    for (int k0 = 0; k0 < kI; k0 += 16) {
        #pragma unroll
        for (int p = 0; p < 2; p++) {
            *(float4*)&As[asoff[p]] = ra[p];   // g_h already tf32-rounded
            float4 v;
            v.x = tf32r(rb[p].x); v.y = tf32r(rb[p].y);
            v.z = tf32r(rb[p].z); v.w = tf32r(rb[p].w);
            *(float4*)&Bs[bsoff[p]] = v;
        }
        __syncthreads();
        if (k0 + 16 < kI) {
            #pragma unroll
            for (int p = 0; p < 2; p++) {
                ra[p] = aval[p] ? *(const float4*)(aptr[p] + k0 + 16)
                                : make_float4(0.f,0.f,0.f,0.f);
                rb[p] = *(const float4*)(bptr[p] + (size_t)(k0 + 16) * kH);
            }
        }
        #pragma unroll
        for (int ks = 0; ks < 16; ks += 8) {
            uint32_t af[2][4];
            #pragma unroll
            for (int mt = 0; mt < 2; mt++) {
                int m = mb + mt * 16;
                af[mt][0] = __float_as_uint(As[(m + qr) * 20 + ks + qc]);
                af[mt][1] = __float_as_uint(As[(m + qr + 8) * 20 + ks + qc]);
                af[mt][2] = __float_as_uint(As[(m + qr) * 20 + ks + qc + 4]);
                af[mt][3] = __float_as_uint(As[(m + qr + 8) * 20 + ks + qc + 4]);
            }
            #pragma unroll
            for (int nt = 0; nt < 8; nt++) {
                int n = nbase + nt * 8 + qr;
                uint32_t b0 = __float_as_uint(Bs[(ks + qc) * 132 + n]);
                uint32_t b1 = __float_as_uint(Bs[(ks + qc + 4) * 132 + n]);
                #pragma unroll
                for (int mt = 0; mt < 2; mt++) {
                    mma8(c[mt][nt][0], c[mt][nt][1], c[mt][nt][2], c[mt][nt][3],
                         af[mt][0], af[mt][1], af[mt][2], af[mt][3], b0, b1);
                }
            }
        }
        __syncthreads();
    }

    #pragma unroll
    for (int mt = 0; mt < 2; mt++) {
        #pragma unroll
        for (int half = 0; half < 2; half++) {
            int r = row0 + mb + mt * 16 + qr + half * 8;
            if (r < cnt) {
                int tok = g_tok[e * kT + r];
                float* op = out + (size_t)tok * kH + col0;
                #pragma unroll
                for (int nt = 0; nt < 8; nt++) {
                    int n = nbase + nt * 8 + 2 * qc;
                    atomicAdd(&op[n],     c[mt][nt][half * 2 + 0]);
                    atomicAdd(&op[n + 1], c[mt][nt][half * 2 + 1]);
                }
            }
        }
    }
}

// ---------------------------------------------------------------------------
extern "C" void kernel_launch(void* const* d_in, const int* in_sizes, int n_in,
                              void* d_out, int out_size) {
    const float* x   = (const float*)d_in[0];
    const float* rw  = (const float*)d_in[1];
    const float* eb  = (const float*)d_in[2];
    const float* wg  = (const float*)d_in[3];
    const float* wu  = (const float*)d_in[4];
    const float* wd  = (const float*)d_in[5];
    const float* swg = (const float*)d_in[6];
    const float* swu = (const float*)d_in[7];
    const float* swd = (const float*)d_in[8];
    float* out = (float*)d_out;

    init_kernel<<<4, 256>>>();
    zero_out_kernel<<<1024, 256>>>((float4*)out);
    router_kernel<<<kT, 512>>>(x, rw, eb);
    gateup_all<<<dim3(8, 8, kEAll), 256>>>(x, wg, wu, swg, swu);
    down_all<<<dim3(8, 8, kEAll), 256>>>(wd, swd, out);
}

// round 3
// speedup vs baseline: 4.0576x; 1.0011x over previous
#include <cuda_runtime.h>
#include <math.h>
#include <stdint.h>

// Problem constants
constexpr int kT    = 1024;   // tokens
constexpr int kH    = 1024;   // hidden
constexpr int kI    = 512;    // routed intermediate
constexpr int kE    = 16;     // routed experts
constexpr int kEAll = 18;     // + 2 shared-expert halves
constexpr int kTopK = 4;
constexpr int kNG   = 4;
constexpr int kGS   = kE / kNG;
constexpr int kTKG  = 2;
constexpr int kISH  = 1024;   // shared intermediate (= 2 * kI)
constexpr float kScale = 2.5f;

// ---- device scratch ----
__device__ int   g_cnt[kEAll];
__device__ int   g_tok[kEAll * kT];
__device__ float g_coef[kEAll * kT];
__device__ float g_h[(size_t)kEAll * kT * kI];   // 37.7 MB

// ---------------------------------------------------------------------------
__device__ __forceinline__ float tf32r(float f) {
    uint32_t r; asm("cvt.rna.tf32.f32 %0, %1;" : "=r"(r) : "f"(f));
    return __uint_as_float(r);
}

__device__ __forceinline__ void mma8(float& c0, float& c1, float& c2, float& c3,
                                     uint32_t a0, uint32_t a1, uint32_t a2, uint32_t a3,
                                     uint32_t b0, uint32_t b1) {
    asm volatile("mma.sync.aligned.m16n8k8.row.col.f32.tf32.tf32.f32 "
                 "{%0,%1,%2,%3},{%4,%5,%6,%7},{%8,%9},{%0,%1,%2,%3};\n"
                 : "+f"(c0), "+f"(c1), "+f"(c2), "+f"(c3)
                 : "r"(a0), "r"(a1), "r"(a2), "r"(a3), "r"(b0), "r"(b1));
}

// ---------------------------------------------------------------------------
__global__ void init_kernel() {
    int i = blockIdx.x * blockDim.x + threadIdx.x;
    if (i < kE) g_cnt[i] = 0;
    if (i == kE || i == kE + 1) g_cnt[i] = kT;
    if (i < kT) {
        g_tok[kE * kT + i] = i;       g_coef[kE * kT + i] = 1.f;
        g_tok[(kE + 1) * kT + i] = i; g_coef[(kE + 1) * kT + i] = 1.f;
    }
}

__global__ void zero_out_kernel(float4* out) {
    int i = blockIdx.x * blockDim.x + threadIdx.x;
    if (i < kT * kH / 4) out[i] = make_float4(0.f, 0.f, 0.f, 0.f);
}

// ---------------------------------------------------------------------------
// Router: one block per token; exact grouped-top-k, scatter with atomics.
__global__ __launch_bounds__(512) void router_kernel(
    const float* __restrict__ x, const float* __restrict__ rw,
    const float* __restrict__ ebias)
{
    const int t = blockIdx.x;
    const int warp = threadIdx.x >> 5;
    const int lane = threadIdx.x & 31;
    __shared__ float logits[kE];

    const float* xr = x + (size_t)t * kH;
    float acc = 0.f;
    for (int h = lane; h < kH; h += 32)
        acc += xr[h] * rw[h * kE + warp];
    #pragma unroll
    for (int o = 16; o; o >>= 1) acc += __shfl_xor_sync(0xffffffffu, acc, o);
    if (lane == 0) logits[warp] = acc;
    __syncthreads();

    if (threadIdx.x == 0) {
        float scores[kE], sc[kE];
        #pragma unroll
        for (int e = 0; e < kE; e++) {
            float s = 1.f / (1.f + expf(-logits[e]));
            scores[e] = s;
            sc[e] = s + ebias[e];
        }
        float gs[kNG];
        #pragma unroll
        for (int g = 0; g < kNG; g++) {
            float m1 = -1e30f, m2 = -1e30f;
            #pragma unroll
            for (int j = 0; j < kGS; j++) {
                float v = sc[g * kGS + j];
                if (v > m1) { m2 = m1; m1 = v; }
                else if (v > m2) m2 = v;
            }
            gs[g] = m1 + m2;
        }
        bool gsel[kNG] = {false, false, false, false};
        for (int k = 0; k < kTKG; k++) {
            int bi = -1; float bv = -1e30f;
            for (int g = 0; g < kNG; g++)
                if (!gsel[g] && gs[g] > bv) { bv = gs[g]; bi = g; }
            gsel[bi] = true;
        }
        float masked[kE];
        #pragma unroll
        for (int e = 0; e < kE; e++)
            masked[e] = gsel[e / kGS] ? sc[e] : 0.f;
        int tidx[kTopK]; float w[kTopK]; float wsum = 0.f;
        bool used[kE];
        #pragma unroll
        for (int e = 0; e < kE; e++) used[e] = false;
        for (int k = 0; k < kTopK; k++) {
            int bi = -1; float bv = -1e30f;
            for (int e = 0; e < kE; e++)
                if (!used[e] && masked[e] > bv) { bv = masked[e]; bi = e; }
            used[bi] = true;
            tidx[k] = bi;
            w[k] = scores[bi];
            wsum += w[k];
        }
        float inv = kScale / (wsum + 1e-20f);
        for (int k = 0; k < kTopK; k++) {
            int e = tidx[k];
            int slot = atomicAdd(&g_cnt[e], 1);
            g_tok[e * kT + slot]  = t;
            g_coef[e * kT + slot] = w[k] * inv;
        }
    }
}

// ---------------------------------------------------------------------------
// Fused gate+up for all 18 experts. Block tile: 128 rows x (64 g + 64 u cols).
// tf32 mma m16n8k8, 8 warps (4M x 2N), warp tile 32x32 on each of g/u.
__global__ __launch_bounds__(256) void gateup_all(
    const float* __restrict__ x, const float* __restrict__ wg,
    const float* __restrict__ wu, const float* __restrict__ swg,
    const float* __restrict__ swu)
{
    const int e = blockIdx.z;
    const int cnt = g_cnt[e];
    const int row0 = blockIdx.y * 128;
    if (row0 >= cnt) return;
    const int col0 = blockIdx.x * 64;

    const float *bg, *bu; int ldb;
    if (e < kE) {
        bg = wg + (size_t)e * kH * kI;
        bu = wu + (size_t)e * kH * kI;
        ldb = kI;
    } else {
        int off = (e - kE) * kI;
        bg = swg + off; bu = swu + off; ldb = kISH;
    }

    __shared__ float As[128 * 20];   // [m][k], stride 20 (conflict-free)
    __shared__ float Bgs[16 * 68];   // [k][n], stride 68
    __shared__ float Bus[16 * 68];

    const int tid = threadIdx.x;

    // A staging: 2 float4/thread (gathered token rows)
    const float* aptr[2]; bool aval[2]; int asoff[2];
    #pragma unroll
    for (int p = 0; p < 2; p++) {
        int j = tid + 256 * p;
        int arow = j >> 2, ac4 = j & 3;
        int r = row0 + arow;
        aval[p] = r < cnt;
        int tok = aval[p] ? g_tok[e * kT + r] : 0;
        aptr[p] = x + (size_t)tok * kH + ac4 * 4;
        asoff[p] = arow * 20 + ac4 * 4;
    }
    // B staging: 1 float4/thread per matrix
    const int bkrow = tid >> 4, bc4 = tid & 15;
    const float* bgp = bg + (size_t)bkrow * ldb + col0 + bc4 * 4;
    const float* bup = bu + (size_t)bkrow * ldb + col0 + bc4 * 4;
    const int bsoff = bkrow * 68 + bc4 * 4;

    const int warp = tid >> 5, lane = tid & 31;
    const int mb = (warp & 3) * 32, nb = (warp >> 2) * 32;
    const int qr = lane >> 2, qc = lane & 3;

    float cg[2][4][4] = {}, cu[2][4][4] = {};

    float4 ra[2], rbg, rbu;
    #pragma unroll
    for (int p = 0; p < 2; p++)
        ra[p] = aval[p] ? *(const float4*)aptr[p] : make_float4(0.f,0.f,0.f,0.f);
    rbg = *(const float4*)bgp;
    rbu = *(const float4*)bup;

    for (int k0 = 0; k0 < kH; k0 += 16) {
        #pragma unroll
        for (int p = 0; p < 2; p++) {
            float4 v;
            v.x = tf32r(ra[p].x); v.y = tf32r(ra[p].y);
            v.z = tf32r(ra[p].z); v.w = tf32r(ra[p].w);
            *(float4*)&As[asoff[p]] = v;
        }
        {
            float4 v;
            v.x = tf32r(rbg.x); v.y = tf32r(rbg.y);
            v.z = tf32r(rbg.z); v.w = tf32r(rbg.w);
            *(float4*)&Bgs[bsoff] = v;
        }
        {
            float4 v;
            v.x = tf32r(rbu.x); v.y = tf32r(rbu.y);
            v.z = tf32r(rbu.z); v.w = tf32r(rbu.w);
            *(float4*)&Bus[bsoff] = v;
        }
        __syncthreads();
        if (k0 + 16 < kH) {
            #pragma unroll
            for (int p = 0; p < 2; p++)
                ra[p] = aval[p] ? *(const float4*)(aptr[p] + k0 + 16)
                                : make_float4(0.f,0.f,0.f,0.f);
            rbg = *(const float4*)(bgp + (size_t)(k0 + 16) * ldb);
            rbu = *(const float4*)(bup + (size_t)(k0 + 16) * ldb);
        }
        #pragma unroll
        for (int ks = 0; ks < 16; ks += 8) {
            uint32_t af[2][4];
            #pragma unroll
            for (int mt = 0; mt < 2; mt++) {
                int m = mb + mt * 16;
                af[mt][0] = __float_as_uint(As[(m + qr) * 20 + ks + qc]);
                af[mt][1] = __float_as_uint(As[(m + qr + 8) * 20 + ks + qc]);
                af[mt][2] = __float_as_uint(As[(m + qr) * 20 + ks + qc + 4]);
                af[mt][3] = __float_as_uint(As[(m + qr + 8) * 20 + ks + qc + 4]);
            }
            #pragma unroll
            for (int nt = 0; nt < 4; nt++) {
                int n = nb + nt * 8 + qr;
                uint32_t b0g = __float_as_uint(Bgs[(ks + qc) * 68 + n]);
                uint32_t b1g = __float_as_uint(Bgs[(ks + qc + 4) * 68 + n]);
                uint32_t b0u = __float_as_uint(Bus[(ks + qc) * 68 + n]);
                uint32_t b1u = __float_as_uint(Bus[(ks + qc + 4) * 68 + n]);
                #pragma unroll
                for (int mt = 0; mt < 2; mt++) {
                    mma8(cg[mt][nt][0], cg[mt][nt][1], cg[mt][nt][2], cg[mt][nt][3],
                         af[mt][0], af[mt][1], af[mt][2], af[mt][3], b0g, b1g);
                    mma8(cu[mt][nt][0], cu[mt][nt][1], cu[mt][nt][2], cu[mt][nt][3],
                         af[mt][0], af[mt][1], af[mt][2], af[mt][3], b0u, b1u);
                }
            }
        }
        __syncthreads();
    }

    // Epilogue: h = coef * silu(g) * u, tf32-pre-rounded for the down GEMM.
    #pragma unroll
    for (int mt = 0; mt < 2; mt++) {
        #pragma unroll
        for (int half = 0; half < 2; half++) {
            int r = row0 + mb + mt * 16 + qr + half * 8;
            if (r < cnt) {
                float cf = g_coef[e * kT + r];
                float* hp = g_h + ((size_t)e * kT + r) * kI + col0;
                #pragma unroll
                for (int nt = 0; nt < 4; nt++) {
                    float g0 = cg[mt][nt][half * 2 + 0];
                    float g1 = cg[mt][nt][half * 2 + 1];
                    float u0 = cu[mt][nt][half * 2 + 0];
                    float u1 = cu[mt][nt][half * 2 + 1];
                    float h0 = cf * (g0 / (1.f + __expf(-g0))) * u0;
                    float h1 = cf * (g1 / (1.f + __expf(-g1))) * u1;
                    float2 st; st.x = tf32r(h0); st.y = tf32r(h1);
                    *(float2*)&hp[nb + nt * 8 + 2 * qc] = st;
                }
            }
        }
    }
}

// ---------------------------------------------------------------------------
// Down-proj for all 18 experts. Block tile 128x128, warp tile 32x64.
// Accumulates into zero-initialized out via atomicAdd (routed + shared).
__global__ __launch_bounds__(256) void down_all(
    const float* __restrict__ wd, const float* __restrict__ swd,
    float* __restrict__ out)
{
    const int e = blockIdx.z;
    const int cnt = g_cnt[e];
    const int row0 = blockIdx.y * 128;
    if (row0 >= cnt) return;
    const int col0 = blockIdx.x * 128;

    const float* bb = (e < kE) ? (wd + (size_t)e * kI * kH)
                               : (swd + (size_t)(e - kE) * kI * kH);

    __shared__ float As[128 * 20];   // [m][k]
    __shared__ float Bs[16 * 132];   // [k][n]

    const int tid = threadIdx.x;

    const float* aptr[2]; bool aval[2]; int asoff[2];
    #pragma unroll
    for (int p = 0; p < 2; p++) {
        int j = tid + 256 * p;
        int arow = j >> 2, ac4 = j & 3;
        int r = row0 + arow;
        aval[p] = r < cnt;
        int rc = aval[p] ? r : 0;
        aptr[p] = g_h + ((size_t)e * kT + rc) * kI + ac4 * 4;
        asoff[p] = arow * 20 + ac4 * 4;
    }
    const float* bptr[2]; int bsoff[2];
    #pragma unroll
    for (int p = 0; p < 2; p++) {
        int j = tid + 256 * p;
        int bkr = j >> 5, bc4 = j & 31;
        bptr[p] = bb + (size_t)bkr * kH + col0 + bc4 * 4;
        bsoff[p] = bkr * 132 + bc4 * 4;
    }

    const int warp = tid >> 5, lane = tid & 31;
    const int mb = (warp & 3) * 32, nbase = (warp >> 2) * 64;
    const int qr = lane >> 2, qc = lane & 3;

    float c[2][8][4] = {};

    float4 ra[2], rb[2];
    #pragma unroll
    for (int p = 0; p < 2; p++) {
        ra[p] = aval[p] ? *(const float4*)aptr[p] : make_float4(0.f,0.f,0.f,0.f);
        rb[p] = *(const float4*)bptr[p];
    }

    for (int k0 = 0; k0 < kI; k0 += 16) {
        #pragma unroll
        for (int p = 0; p < 2; p++) {
            *(float4*)&As[asoff[p]] = ra[p];   // g_h already tf32-rounded
            float4 v;
            v.x = tf32r(rb[p].x); v.y = tf32r(rb[p].y);
            v.z = tf32r(rb[p].z); v.w = tf32r(rb[p].w);
            *(float4*)&Bs[bsoff[p]] = v;
        }
        __syncthreads();
        if (k0 + 16 < kI) {
            #pragma unroll
            for (int p = 0; p < 2; p++) {
                ra[p] = aval[p] ? *(const float4*)(aptr[p] + k0 + 16)
                                : make_float4(0.f,0.f,0.f,0.f);
                rb[p] = *(const float4*)(bptr[p] + (size_t)(k0 + 16) * kH);
            }
        }
        #pragma unroll
        for (int ks = 0; ks < 16; ks += 8) {
            uint32_t af[2][4];
            #pragma unroll
            for (int mt = 0; mt < 2; mt++) {
                int m = mb + mt * 16;
                af[mt][0] = __float_as_uint(As[(m + qr) * 20 + ks + qc]);
                af[mt][1] = __float_as_uint(As[(m + qr + 8) * 20 + ks + qc]);
                af[mt][2] = __float_as_uint(As[(m + qr) * 20 + ks + qc + 4]);
                af[mt][3] = __float_as_uint(As[(m + qr + 8) * 20 + ks + qc + 4]);
            }
            #pragma unroll
            for (int nt = 0; nt < 8; nt++) {
                int n = nbase + nt * 8 + qr;
                uint32_t b0 = __float_as_uint(Bs[(ks + qc) * 132 + n]);
                uint32_t b1 = __float_as_uint(Bs[(ks + qc + 4) * 132 + n]);
                #pragma unroll
                for (int mt = 0; mt < 2; mt++) {
                    mma8(c[mt][nt][0], c[mt][nt][1], c[mt][nt][2], c[mt][nt][3],
                         af[mt][0], af[mt][1], af[mt][2], af[mt][3], b0, b1);
                }
            }
        }
        __syncthreads();
    }

    #pragma unroll
    for (int mt = 0; mt < 2; mt++) {
        #pragma unroll
        for (int half = 0; half < 2; half++) {
            int r = row0 + mb + mt * 16 + qr + half * 8;
            if (r < cnt) {
                int tok = g_tok[e * kT + r];
                float* op = out + (size_t)tok * kH + col0;
                #pragma unroll
                for (int nt = 0; nt < 8; nt++) {
                    int n = nbase + nt * 8 + 2 * qc;
                    atomicAdd(&op[n],     c[mt][nt][half * 2 + 0]);
                    atomicAdd(&op[n + 1], c[mt][nt][half * 2 + 1]);
                }
            }
        }
    }
}

// ---------------------------------------------------------------------------
extern "C" void kernel_launch(void* const* d_in, const int* in_sizes, int n_in,
                              void* d_out, int out_size) {
    const float* x   = (const float*)d_in[0];
    const float* rw  = (const float*)d_in[1];
    const float* eb  = (const float*)d_in[2];
    const float* wg  = (const float*)d_in[3];
    const float* wu  = (const float*)d_in[4];
    const float* wd  = (const float*)d_in[5];
    const float* swg = (const float*)d_in[6];
    const float* swu = (const float*)d_in[7];
    const float* swd = (const float*)d_in[8];
    float* out = (float*)d_out;

    init_kernel<<<4, 256>>>();
    zero_out_kernel<<<1024, 256>>>((float4*)out);
    router_kernel<<<kT, 512>>>(x, rw, eb);
    gateup_all<<<dim3(8, 8, kEAll), 256>>>(x, wg, wu, swg, swu);
    down_all<<<dim3(8, 8, kEAll), 256>>>(wd, swd, out);
}